// round 14
// baseline (speedup 1.0000x reference)
#include <cuda_runtime.h>
#include <cuda_fp16.h>
#include <stdint.h>

#define B_SZ     4096
#define D0       1024
#define D1       8192
#define D2       8192
#define D3       10240
#define NNEUR    (D1 + D2 + D3)     // 26624
#define KCLS     10
#define GRP      (D3 / KCLS)        // 1024
#define TAU      30.0f
#define ROWS     2                  // batch rows per CTA -> 4B slots, 2 CTAs/SM
#define NTHREADS 1024
#define NWARP    (NTHREADS / 32)    // 32
#define CELLSA   32                 // a-bank residues (mod 32, 4B banks)
#define CELLSB   16                 // b residues (mod 16)
#define CELLS    (CELLSA * CELLSB)  // 512
#define CHUNK    1024
#define CAP      (CHUNK / CELLS)    // 2
#define NCHUNK   (NNEUR / CHUNK)    // 26
#define SCNSTR   36                 // 32 warps + pad

// -------- inverse perms (orig -> dealt pos, layer-local) --------
__device__ uint16_t d_inv1[D1];
__device__ uint16_t d_inv2[D2];
// -------- final metadata (dealt positions) --------
__device__ uint32_t g_idx[NNEUR];   // ia | (ib<<16) (raw after build; remapped after remap)
__device__ uint2    g_coef[NNEUR];  // {half2(c0,c1), half2(c2,c3)}

__constant__ float OPC[16][4] = {
    {0.f, 0.f, 0.f, 0.f}, {0.f, 0.f, 0.f, 1.f}, {0.f, 1.f, 0.f, -1.f}, {0.f, 1.f, 0.f, 0.f},
    {0.f, 0.f, 1.f, -1.f}, {0.f, 0.f, 1.f, 0.f}, {0.f, 1.f, 1.f, -2.f}, {0.f, 1.f, 1.f, -1.f},
    {1.f, -1.f, -1.f, 1.f}, {1.f, -1.f, -1.f, 2.f}, {1.f, 0.f, -1.f, 0.f}, {1.f, 0.f, -1.f, 1.f},
    {1.f, -1.f, 0.f, 0.f}, {1.f, -1.f, 0.f, 1.f}, {1.f, 0.f, 0.f, -1.f}, {1.f, 0.f, 0.f, 0.f}};

// ---- single parallel build launch: 26 independent CTAs ---------------------
// Folds softmax precompute + bank-deal + inv publication. Cell classification:
//   L1: exact (x unpermuted):      ra = ia1[j]&31,           rb = ib1[j]&15
//   L2: inv1[a]&31 == ia1[a]&31 for seated sources (~73%):   ra = ia1[ia2[j]]&31
//   L3: inv2[a]&31 == ia1[ia2[a]]&31 for seated (~73%)
// Prediction quality only affects conflict rates; permutation itself is exact.
// g_idx holds RAW indices here; remap_kernel translates L2/L3 exactly.
__global__ void __launch_bounds__(1024, 1)
build_kernel(const float* __restrict__ w1, const float* __restrict__ w2,
             const float* __restrict__ w3,
             const int* __restrict__ ia1, const int* __restrict__ ib1,
             const int* __restrict__ ia2, const int* __restrict__ ib2,
             const int* __restrict__ ia3, const int* __restrict__ ib3)
{
    __shared__ uint16_t off[CELLS * SCNSTR];   // per (cell,warp) counts -> exclusive
    __shared__ uint16_t chb[CELLS * 2];        // per (cell, 16-warp half) bases
    __shared__ uint16_t csize[CELLS], exo[CELLS], ufo[CELLS];
    __shared__ uint16_t ufp[CHUNK];
    __shared__ int wte[16], wtu[16];

    const int tid  = threadIdx.x;
    const int lane = tid & 31;
    const int w    = tid >> 5;
    const uint32_t ltm = (1u << lane) - 1u;

    const int chunk = blockIdx.x;
    const int layer = (chunk < 8) ? 0 : ((chunk < 16) ? 1 : 2);
    const int layerBase = (layer == 0) ? 0 : ((layer == 1) ? D1 : (D1 + D2));
    const int baseL = (chunk - ((layer == 0) ? 0 : ((layer == 1) ? 8 : 16))) * CHUNK;
    const int j = baseL + tid;

    // ---- indices + residue predictions ----
    int ia, ib; const float* wp;
    uint32_t ra, rb;
    if (layer == 0) {
        ia = __ldg(&ia1[j]); ib = __ldg(&ib1[j]); wp = w1 + (size_t)j * 16;
        ra = (uint32_t)ia & 31u;
        rb = (uint32_t)ib & 15u;
    } else if (layer == 1) {
        ia = __ldg(&ia2[j]); ib = __ldg(&ib2[j]); wp = w2 + (size_t)j * 16;
        ra = (uint32_t)__ldg(&ia1[ia]) & 31u;
        rb = (uint32_t)__ldg(&ia1[ib]) & 15u;
    } else {
        ia = __ldg(&ia3[j]); ib = __ldg(&ib3[j]); wp = w3 + (size_t)j * 16;
        ra = (uint32_t)__ldg(&ia1[__ldg(&ia2[ia])]) & 31u;
        rb = (uint32_t)__ldg(&ia1[__ldg(&ia2[ib])]) & 15u;
    }

    // ---- softmax coefficients ----
    float v[16]; float m = -3.4e38f;
#pragma unroll
    for (int i = 0; i < 16; i++) { v[i] = wp[i]; m = fmaxf(m, v[i]); }
    float s = 0.f;
#pragma unroll
    for (int i = 0; i < 16; i++) { v[i] = expf(v[i] - m); s += v[i]; }
    float inv = 1.f / s;
    float c0 = 0.f, c1 = 0.f, c2 = 0.f, c3 = 0.f;
#pragma unroll
    for (int i = 0; i < 16; i++) {
        float p = v[i] * inv;
        c0 = fmaf(p, OPC[i][0], c0);
        c1 = fmaf(p, OPC[i][1], c1);
        c2 = fmaf(p, OPC[i][2], c2);
        c3 = fmaf(p, OPC[i][3], c3);
    }
    __half2 h01 = __floats2half2_rn(c0, c1);
    __half2 h23 = __floats2half2_rn(c2, c3);
    uint2 coef = make_uint2(*reinterpret_cast<uint32_t*>(&h01),
                            *reinterpret_cast<uint32_t*>(&h23));

    // ---- deal ----
    for (int i = tid; i < CELLS * SCNSTR / 2; i += NTHREADS)
        reinterpret_cast<uint32_t*>(off)[i] = 0;
    __syncthreads();

    int cell = (int)(ra * 16u + rb);           // t = cell>>4 in [0,32), s = cell&15
    uint32_t mask = __match_any_sync(0xffffffffu, cell);
    int lr = __popc(mask & ltm);
    if ((mask & ltm) == 0)
        off[cell * SCNSTR + w] = (uint16_t)__popc(mask);
    __syncthreads();

    {   // phase 1: per-(cell, 16-warp half) exclusive scan  (512 cells x 2)
        int c  = tid >> 1;
        int ch = tid & 1;
        int bo = c * SCNSTR + ch * 16;
        uint16_t run = 0;
#pragma unroll
        for (int i = 0; i < 16; i++) {
            uint16_t t = off[bo + i];
            off[bo + i] = run;
            run = (uint16_t)(run + t);
        }
        chb[c * 2 + ch] = run;
    }
    __syncthreads();

    if (tid < CELLS) {   // phase 2: per-cell combine
        int c = tid;
        uint16_t t0 = chb[c * 2 + 0];
        uint16_t t1 = chb[c * 2 + 1];
        chb[c * 2 + 0] = 0;
        chb[c * 2 + 1] = t0;
        uint16_t sz = (uint16_t)(t0 + t1);
        csize[c] = sz;
        exo[c] = (sz > CAP) ? (uint16_t)(sz - CAP) : 0;
        ufo[c] = (sz < CAP) ? (uint16_t)(CAP - sz) : 0;
    }
    __syncthreads();

    {   // inclusive scans over 512 cells via warp shuffles (warps 0..15)
        int e = 0, u = 0;
        if (tid < CELLS) {
            e = exo[tid]; u = ufo[tid];
#pragma unroll
            for (int o = 1; o < 32; o <<= 1) {
                int pe = __shfl_up_sync(0xffffffffu, e, o);
                int pu = __shfl_up_sync(0xffffffffu, u, o);
                if (lane >= o) { e += pe; u += pu; }
            }
            if (lane == 31) { wte[w] = e; wtu[w] = u; }
        }
        __syncthreads();
        if (tid == 0) {
            int be = 0, bu = 0;
#pragma unroll
            for (int i = 0; i < 16; i++) {
                int te = wte[i], tu = wtu[i];
                wte[i] = be; wtu[i] = bu;
                be += te; bu += tu;
            }
        }
        __syncthreads();
        if (tid < CELLS) {
            exo[tid] = (uint16_t)(e + wte[w]);
            ufo[tid] = (uint16_t)(u + wtu[w]);
        }
    }
    __syncthreads();

    if (tid < CELLS) {   // emit unfilled dealt positions, grouped by cell
        int c = tid, t = c >> 4, ss = c & 15;
        int sz  = csize[c];
        int ufc = (sz < CAP) ? CAP - sz : 0;
        int ub  = ufo[c] - ufc;
        for (int mm = sz; mm < CAP; mm++)
            ufp[ub + (mm - sz)] = (uint16_t)((((ss - t) & 15) + 16 * mm) * 32 + t);
    }
    __syncthreads();

    int p;
    {   // assign position
        int grank = off[cell * SCNSTR + w] + chb[cell * 2 + (w >> 4)] + lr;
        int t = cell >> 4, ss = cell & 15;
        if (grank < CAP) {
            p = (((ss - t) & 15) + 16 * grank) * 32 + t;
        } else {
            int exc = csize[cell] - CAP;
            int exb = exo[cell] - exc;
            p = ufp[exb + (grank - CAP)];
        }
    }
    const int dstPos = layerBase + baseL + p;
    g_idx[dstPos]  = (uint32_t)ia | ((uint32_t)ib << 16);  // raw; remap fixes L2/L3
    g_coef[dstPos] = coef;
    if (layer == 0)      d_inv1[j] = (uint16_t)(baseL + p);
    else if (layer == 1) d_inv2[j] = (uint16_t)(baseL + p);
}

// ---- remap: rewrite layer-2/3 gather indices into dealt position space -----
__global__ void remap_kernel()
{
    int s = blockIdx.x * blockDim.x + threadIdx.x;
    if (s >= D2 + D3) return;
    int idx = D1 + s;
    uint32_t pk = g_idx[idx];
    uint32_t a, b;
    if (s < D2) { a = d_inv1[pk & 0xffffu]; b = d_inv1[pk >> 16]; }
    else        { a = d_inv2[pk & 0xffffu]; b = d_inv2[pk >> 16]; }
    g_idx[idx] = a | (b << 16);
}

// -------- main kernel: ROWS=2, 2 CTAs/SM (R6 body), dealt gathers -----------
// Metadata produced by PRIOR launches -> __ldg legal.

struct NeuronIn {
    uint32_t pk, u01, u23;
    uint32_t a, b;           // half2 each
};

__device__ __forceinline__ void fetch_neuron(const uint32_t* __restrict__ src,
                                             int mj, NeuronIn& n)
{
    n.pk = __ldg(&g_idx[mj]);
    uint2 cc = __ldg(&g_coef[mj]);
    n.u01 = cc.x;
    n.u23 = cc.y;
    n.a = src[n.pk & 0xffffu];
    n.b = src[n.pk >> 16];
}

__device__ __forceinline__ uint32_t neuron_math(const NeuronIn& n)
{
    float2 c01 = __half22float2(*reinterpret_cast<const __half2*>(&n.u01));
    float2 c23 = __half22float2(*reinterpret_cast<const __half2*>(&n.u23));
    float2 a = __half22float2(*reinterpret_cast<const __half2*>(&n.a));
    float2 b = __half22float2(*reinterpret_cast<const __half2*>(&n.b));
    float o0 = fmaf(fmaf(c23.y, b.x, c01.y), a.x, fmaf(c23.x, b.x, c01.x));
    float o1 = fmaf(fmaf(c23.y, b.y, c01.y), a.y, fmaf(c23.x, b.y, c01.x));
    __half2 h = __floats2half2_rn(o0, o1);
    return *reinterpret_cast<uint32_t*>(&h);
}

__device__ __forceinline__ void run_layer(const uint32_t* __restrict__ src,
                                          uint32_t* __restrict__ dst,
                                          int metaBase, int D, int tid)
{
    const int iters = D / NTHREADS;
    NeuronIn cur, nxt;
    int j = tid;
    fetch_neuron(src, metaBase + j, cur);
#pragma unroll 2
    for (int it = 0; it < iters - 1; it++) {
        fetch_neuron(src, metaBase + j + NTHREADS, nxt);
        dst[j] = neuron_math(cur);
        cur = nxt;
        j += NTHREADS;
    }
    dst[j] = neuron_math(cur);
}

__global__ void __launch_bounds__(NTHREADS, 2)
diff_logic_main(const float* __restrict__ x, float* __restrict__ out)
{
    extern __shared__ __align__(16) uint32_t smem_raw[];
    uint32_t* xs = smem_raw;                          // D0 slots (half2 each)
    uint32_t* h1 = xs + D0;
    uint32_t* h2 = h1 + D1;
    float* wacc = reinterpret_cast<float*>(h2 + D2);

    const int tid  = threadIdx.x;
    const int row0 = blockIdx.x * ROWS;               // exact: 4096 = 2048*2

    {   // load 2 batch rows of x: thread owns column tid (D0 == NTHREADS)
        int col = tid;
        float v0 = __ldg(&x[(size_t)(row0 + 0) * D0 + col]);
        float v1 = __ldg(&x[(size_t)(row0 + 1) * D0 + col]);
        __half2 p = __floats2half2_rn(v0, v1);
        xs[col] = *reinterpret_cast<uint32_t*>(&p);
    }
    __syncthreads();

    run_layer(xs, h1, 0, D1, tid);
    __syncthreads();
    run_layer(h1, h2, D1, D2, tid);
    __syncthreads();

    // Layer 3 fused with group-sum (position perm stays within each group).
    const int lane = tid & 31;
    const int warp = tid >> 5;

    for (int g = 0; g < KCLS; g++) {
        float acc0, acc1;
        {   // GRP == NTHREADS: one neuron per thread per group
            int mj = D1 + D2 + g * GRP + tid;
            NeuronIn n;
            fetch_neuron(h2, mj, n);
            float2 c01 = __half22float2(*reinterpret_cast<const __half2*>(&n.u01));
            float2 c23 = __half22float2(*reinterpret_cast<const __half2*>(&n.u23));
            float2 a = __half22float2(*reinterpret_cast<const __half2*>(&n.a));
            float2 b = __half22float2(*reinterpret_cast<const __half2*>(&n.b));
            acc0 = fmaf(fmaf(c23.y, b.x, c01.y), a.x, fmaf(c23.x, b.x, c01.x));
            acc1 = fmaf(fmaf(c23.y, b.y, c01.y), a.y, fmaf(c23.x, b.y, c01.x));
        }
#pragma unroll
        for (int off = 16; off > 0; off >>= 1) {
            acc0 += __shfl_down_sync(0xffffffffu, acc0, off);
            acc1 += __shfl_down_sync(0xffffffffu, acc1, off);
        }
        if (lane == 0) {
            wacc[(g * NWARP + warp) * ROWS + 0] = acc0;
            wacc[(g * NWARP + warp) * ROWS + 1] = acc1;
        }
    }
    __syncthreads();

    if (tid < KCLS * ROWS) {
        int g = tid / ROWS;
        int r = tid - g * ROWS;
        float s = 0.f;
#pragma unroll
        for (int w = 0; w < NWARP; w++)
            s += wacc[(g * NWARP + w) * ROWS + r];
        out[(size_t)(row0 + r) * KCLS + g] = s * (1.f / TAU);
    }
}

// -----------------------------------------------------------------------------

extern "C" void kernel_launch(void* const* d_in, const int* in_sizes, int n_in,
                              void* d_out, int out_size)
{
    (void)in_sizes; (void)n_in; (void)out_size;
    const float* x  = (const float*)d_in[0];
    const float* w1 = (const float*)d_in[1];
    const float* w2 = (const float*)d_in[2];
    const float* w3 = (const float*)d_in[3];
    const int* ia1 = (const int*)d_in[4];
    const int* ib1 = (const int*)d_in[5];
    const int* ia2 = (const int*)d_in[6];
    const int* ib2 = (const int*)d_in[7];
    const int* ia3 = (const int*)d_in[8];
    const int* ib3 = (const int*)d_in[9];
    float* out = (float*)d_out;

    build_kernel<<<NCHUNK, 1024>>>(w1, w2, w3, ia1, ib1, ia2, ib2, ia3, ib3);
    remap_kernel<<<(D2 + D3 + 255) / 256, 256>>>();

    size_t smem = (size_t)(D0 + D1 + D2) * sizeof(uint32_t)
                + (size_t)(KCLS * NWARP * ROWS) * sizeof(float);   // 69,120 B
    cudaFuncSetAttribute(diff_logic_main, cudaFuncAttributeMaxDynamicSharedMemorySize, (int)smem);

    diff_logic_main<<<B_SZ / ROWS, NTHREADS, smem>>>(x, out);
}

// round 15
// speedup vs baseline: 1.1840x; 1.1840x over previous
#include <cuda_runtime.h>
#include <cuda_fp16.h>
#include <stdint.h>

#define B_SZ     4096
#define D0       1024
#define D1       8192
#define D2       8192
#define D3       10240
#define NNEUR    (D1 + D2 + D3)     // 26624
#define KCLS     10
#define GRP      (D3 / KCLS)        // 1024
#define TAU      30.0f
#define ROWS     4                  // batch rows per CTA (4096/4 = 1024 CTAs)
#define NTHREADS 1024
#define NWARP    (NTHREADS / 32)    // 32

// -------- precomputed per-neuron metadata (device globals, no allocs) --------
__device__ __align__(16) uint32_t g_idx[NNEUR];   // ia | (ib<<16)
__device__ __align__(16) uint2    g_coef[NNEUR];  // {half2(c0,c1), half2(c2,c3)}

__constant__ float OPC[16][4] = {
    {0.f, 0.f, 0.f, 0.f}, {0.f, 0.f, 0.f, 1.f}, {0.f, 1.f, 0.f, -1.f}, {0.f, 1.f, 0.f, 0.f},
    {0.f, 0.f, 1.f, -1.f}, {0.f, 0.f, 1.f, 0.f}, {0.f, 1.f, 1.f, -2.f}, {0.f, 1.f, 1.f, -1.f},
    {1.f, -1.f, -1.f, 1.f}, {1.f, -1.f, -1.f, 2.f}, {1.f, 0.f, -1.f, 0.f}, {1.f, 0.f, -1.f, 1.f},
    {1.f, -1.f, 0.f, 0.f}, {1.f, -1.f, 0.f, 1.f}, {1.f, 0.f, 0.f, -1.f}, {1.f, 0.f, 0.f, 0.f}};

__global__ void precompute_kernel(
    const float* __restrict__ w1, const float* __restrict__ w2, const float* __restrict__ w3,
    const int* __restrict__ ia1, const int* __restrict__ ib1,
    const int* __restrict__ ia2, const int* __restrict__ ib2,
    const int* __restrict__ ia3, const int* __restrict__ ib3)
{
    int j = blockIdx.x * blockDim.x + threadIdx.x;
    if (j >= NNEUR) return;
    const float* w; int ia, ib;
    if (j < D1)            { w = w1 + (size_t)j * 16;               ia = ia1[j];            ib = ib1[j]; }
    else if (j < D1 + D2)  { int k = j - D1;      w = w2 + (size_t)k * 16; ia = ia2[k]; ib = ib2[k]; }
    else                   { int k = j - D1 - D2; w = w3 + (size_t)k * 16; ia = ia3[k]; ib = ib3[k]; }

    float v[16]; float m = -3.4e38f;
#pragma unroll
    for (int i = 0; i < 16; i++) { v[i] = w[i]; m = fmaxf(m, v[i]); }
    float s = 0.f;
#pragma unroll
    for (int i = 0; i < 16; i++) { v[i] = expf(v[i] - m); s += v[i]; }
    float inv = 1.f / s;
    float c0 = 0.f, c1 = 0.f, c2 = 0.f, c3 = 0.f;
#pragma unroll
    for (int i = 0; i < 16; i++) {
        float p = v[i] * inv;
        c0 = fmaf(p, OPC[i][0], c0);
        c1 = fmaf(p, OPC[i][1], c1);
        c2 = fmaf(p, OPC[i][2], c2);
        c3 = fmaf(p, OPC[i][3], c3);
    }
    g_idx[j] = (uint32_t)ia | ((uint32_t)ib << 16);
    __half2 h01 = __floats2half2_rn(c0, c1);
    __half2 h23 = __floats2half2_rn(c2, c3);
    g_coef[j] = make_uint2(*reinterpret_cast<uint32_t*>(&h01),
                           *reinterpret_cast<uint32_t*>(&h23));
}

// -------- main kernel: whole network in smem; paired neurons for 2x MLP -----

struct PairIn {
    uint2 idx;               // 2 packed (ia|ib<<16)
    uint4 coef;              // 2 x {c01, c23}
    uint2 a0, b0, a1, b1;    // gathered operands (4 rows as 2x half2 each)
};

__device__ __forceinline__ void fetch_pair(const uint2* __restrict__ src,
                                           int pairIdx, PairIn& p)
{
    p.idx  = __ldg(reinterpret_cast<const uint2*>(g_idx) + pairIdx);
    p.coef = __ldg(reinterpret_cast<const uint4*>(g_coef) + pairIdx);
    p.a0 = src[p.idx.x & 0xffffu];
    p.b0 = src[p.idx.x >> 16];
    p.a1 = src[p.idx.y & 0xffffu];
    p.b1 = src[p.idx.y >> 16];
}

__device__ __forceinline__ uint2 one_neuron(uint32_t u01, uint32_t u23,
                                            uint2 av, uint2 bv)
{
    float2 c01 = __half22float2(*reinterpret_cast<const __half2*>(&u01));
    float2 c23 = __half22float2(*reinterpret_cast<const __half2*>(&u23));
    uint2 o;
#pragma unroll
    for (int r = 0; r < 2; r++) {
        uint32_t ua = (r == 0) ? av.x : av.y;
        uint32_t ub = (r == 0) ? bv.x : bv.y;
        float2 a = __half22float2(*reinterpret_cast<const __half2*>(&ua));
        float2 b = __half22float2(*reinterpret_cast<const __half2*>(&ub));
        // c0 + c1*a + c2*b + c3*a*b = (c1 + c3*b)*a + (c0 + c2*b)
        float o0 = fmaf(fmaf(c23.y, b.x, c01.y), a.x, fmaf(c23.x, b.x, c01.x));
        float o1 = fmaf(fmaf(c23.y, b.y, c01.y), a.y, fmaf(c23.x, b.y, c01.x));
        __half2 h = __floats2half2_rn(o0, o1);
        uint32_t uh = *reinterpret_cast<uint32_t*>(&h);
        if (r == 0) o.x = uh; else o.y = uh;
    }
    return o;
}

// Thread t handles neurons (win + 2t, win + 2t + 1); windows of 2048.
// Output pair -> one STS.128 at uint4 slot (win/2 + t).
__device__ __forceinline__ void run_layer(const uint2* __restrict__ src,
                                          uint2* __restrict__ dst,
                                          int metaBase, int D, int tid)
{
    const int iters = D / (2 * NTHREADS);      // D1,D2: 4
    uint4* dst4 = reinterpret_cast<uint4*>(dst);
    const int pairBase = metaBase / 2;

    PairIn cur, nxt;
    fetch_pair(src, pairBase + tid, cur);
#pragma unroll
    for (int it = 0; it < iters - 1; it++) {
        fetch_pair(src, pairBase + (it + 1) * NTHREADS + tid, nxt);
        uint2 o0 = one_neuron(cur.coef.x, cur.coef.y, cur.a0, cur.b0);
        uint2 o1 = one_neuron(cur.coef.z, cur.coef.w, cur.a1, cur.b1);
        dst4[it * NTHREADS + tid] = make_uint4(o0.x, o0.y, o1.x, o1.y);
        cur = nxt;
    }
    uint2 o0 = one_neuron(cur.coef.x, cur.coef.y, cur.a0, cur.b0);
    uint2 o1 = one_neuron(cur.coef.z, cur.coef.w, cur.a1, cur.b1);
    dst4[(iters - 1) * NTHREADS + tid] = make_uint4(o0.x, o0.y, o1.x, o1.y);
}

__global__ void __launch_bounds__(NTHREADS, 1)
diff_logic_main(const float* __restrict__ x, float* __restrict__ out)
{
    extern __shared__ __align__(16) uint32_t smem_raw[];
    uint2* xs = reinterpret_cast<uint2*>(smem_raw);
    uint2* h1 = xs + D0;
    uint2* h2 = h1 + D1;
    float* wacc = reinterpret_cast<float*>(h2 + D2);

    const int tid  = threadIdx.x;
    const int row0 = blockIdx.x * ROWS;       // exact: 4096 = 1024*4

    {
        int col = tid;                        // D0 == NTHREADS
        float v0 = __ldg(&x[(size_t)(row0 + 0) * D0 + col]);
        float v1 = __ldg(&x[(size_t)(row0 + 1) * D0 + col]);
        float v2 = __ldg(&x[(size_t)(row0 + 2) * D0 + col]);
        float v3 = __ldg(&x[(size_t)(row0 + 3) * D0 + col]);
        __half2 p0 = __floats2half2_rn(v0, v1);
        __half2 p1 = __floats2half2_rn(v2, v3);
        uint2 slot;
        slot.x = *reinterpret_cast<uint32_t*>(&p0);
        slot.y = *reinterpret_cast<uint32_t*>(&p1);
        xs[col] = slot;
    }
    __syncthreads();

    run_layer(xs, h1, 0, D1, tid);
    __syncthreads();
    run_layer(h1, h2, D1, D2, tid);
    __syncthreads();

    // Layer 3 fused with group-sum: 2 neurons per thread per group (paired),
    // threads 0..511 active per pair-lane; keep full-width by letting each
    // thread take pair index tid within group halves: simpler — one neuron per
    // thread, two passes folded into the paired fetch below.
    const int lane = tid & 31;
    const int warp = tid >> 5;

    for (int g = 0; g < KCLS; g++) {
        // pair tid covers neurons 2*tid, 2*tid+1 of group g for tid < 512;
        // to keep all 1024 threads busy, split: thread handles ONE neuron via
        // the classic path (GRP == NTHREADS).
        float acc[ROWS];
        {
            int mj = D1 + D2 + g * GRP + tid;
            uint32_t pk = __ldg(&g_idx[mj]);
            uint2 cc = __ldg(&g_coef[mj]);
            uint2 av = h2[pk & 0xffffu];
            uint2 bv = h2[pk >> 16];
            float2 c01 = __half22float2(*reinterpret_cast<const __half2*>(&cc.x));
            float2 c23 = __half22float2(*reinterpret_cast<const __half2*>(&cc.y));
#pragma unroll
            for (int r = 0; r < 2; r++) {
                uint32_t ua = (r == 0) ? av.x : av.y;
                uint32_t ub = (r == 0) ? bv.x : bv.y;
                float2 a = __half22float2(*reinterpret_cast<const __half2*>(&ua));
                float2 b = __half22float2(*reinterpret_cast<const __half2*>(&ub));
                acc[2 * r + 0] = fmaf(fmaf(c23.y, b.x, c01.y), a.x, fmaf(c23.x, b.x, c01.x));
                acc[2 * r + 1] = fmaf(fmaf(c23.y, b.y, c01.y), a.y, fmaf(c23.x, b.y, c01.x));
            }
        }
#pragma unroll
        for (int r = 0; r < ROWS; r++) {
#pragma unroll
            for (int off = 16; off > 0; off >>= 1)
                acc[r] += __shfl_down_sync(0xffffffffu, acc[r], off);
        }
        if (lane == 0) {
#pragma unroll
            for (int r = 0; r < ROWS; r++)
                wacc[(g * NWARP + warp) * ROWS + r] = acc[r];
        }
    }
    __syncthreads();

    if (tid < KCLS * ROWS) {
        int g = tid / ROWS;
        int r = tid - g * ROWS;
        float s = 0.f;
#pragma unroll
        for (int w = 0; w < NWARP; w++)
            s += wacc[(g * NWARP + w) * ROWS + r];
        out[(size_t)(row0 + r) * KCLS + g] = s * (1.f / TAU);
    }
}

// -----------------------------------------------------------------------------

extern "C" void kernel_launch(void* const* d_in, const int* in_sizes, int n_in,
                              void* d_out, int out_size)
{
    (void)in_sizes; (void)n_in; (void)out_size;
    const float* x  = (const float*)d_in[0];
    const float* w1 = (const float*)d_in[1];
    const float* w2 = (const float*)d_in[2];
    const float* w3 = (const float*)d_in[3];
    const int* ia1 = (const int*)d_in[4];
    const int* ib1 = (const int*)d_in[5];
    const int* ia2 = (const int*)d_in[6];
    const int* ib2 = (const int*)d_in[7];
    const int* ia3 = (const int*)d_in[8];
    const int* ib3 = (const int*)d_in[9];
    float* out = (float*)d_out;

    precompute_kernel<<<(NNEUR + 255) / 256, 256>>>(w1, w2, w3, ia1, ib1, ia2, ib2, ia3, ib3);

    size_t smem = (size_t)(D0 + D1 + D2) * sizeof(uint2)
                + (size_t)(KCLS * NWARP * ROWS) * sizeof(float);   // 144,384 B
    cudaFuncSetAttribute(diff_logic_main, cudaFuncAttributeMaxDynamicSharedMemorySize, (int)smem);

    diff_logic_main<<<B_SZ / ROWS, NTHREADS, smem>>>(x, out);
}

// round 16
// speedup vs baseline: 1.4858x; 1.2549x over previous
#include <cuda_runtime.h>
#include <cuda_fp16.h>
#include <stdint.h>

#define B_SZ     4096
#define D0       1024
#define D1       8192
#define D2       8192
#define D3       10240
#define NNEUR    (D1 + D2 + D3)     // 26624
#define KCLS     10
#define GRP      (D3 / KCLS)        // 1024
#define TAU      30.0f
#define ROWS     4
#define NTHREADS 1024
#define CELLS    256                // 16 a-residues x 16 b-residues (mod 16)
#define CHUNK    1024
#define CAP      (CHUNK / CELLS)    // 4
#define NCHUNK   (NNEUR / CHUNK)    // 26
#define SCNSTR   40                 // 32 warps + pad
// paired metadata bases (in pair units)
#define PB1      0                  // layer1: 4096 pairs
#define PB2      4096               // layer2: 4096 pairs
#define PB3      8192               // layer3: 5120 pairs

// -------- inverse perms (orig -> dealt pos, layer-local) --------
__device__ uint16_t d_inv1[D1];
__device__ uint16_t d_inv2[D2];
// -------- final metadata, PAIRED layout --------
// pair slot s holds two neurons; idx at [2s,2s+1], coef at [4s..4s+3]
__device__ __align__(16) uint32_t g_pidx[NNEUR];       // packed ia|ib<<16
__device__ __align__(16) uint32_t g_pcoef[NNEUR * 2];  // {c01,c23} per neuron

__constant__ float OPC[16][4] = {
    {0.f, 0.f, 0.f, 0.f}, {0.f, 0.f, 0.f, 1.f}, {0.f, 1.f, 0.f, -1.f}, {0.f, 1.f, 0.f, 0.f},
    {0.f, 0.f, 1.f, -1.f}, {0.f, 0.f, 1.f, 0.f}, {0.f, 1.f, 1.f, -2.f}, {0.f, 1.f, 1.f, -1.f},
    {1.f, -1.f, -1.f, 1.f}, {1.f, -1.f, -1.f, 2.f}, {1.f, 0.f, -1.f, 0.f}, {1.f, 0.f, -1.f, 1.f},
    {1.f, -1.f, 0.f, 0.f}, {1.f, -1.f, 0.f, 1.f}, {1.f, 0.f, 0.f, -1.f}, {1.f, 0.f, 0.f, 0.f}};

// paired slot mapping: (layer-local dealt pos) -> (pair slot, half)
__device__ __forceinline__ void pair_slot(int layer, int lpos, int& slot, int& half)
{
    if (layer < 2) { slot = (lpos >> 11) * 1024 + (lpos & 1023); half = (lpos >> 10) & 1; }
    else           { slot = (lpos >> 10) * 512  + (lpos & 511);  half = (lpos >> 9) & 1; }
}

// ---- ONE parallel build launch: 26 independent CTAs (R8-validated deal core)
// Residue classification from raw index chains (exact iff source seated ~81%):
//   L1: ra=ia1[j]&15 (exact)   L2: ra=ia1[ia2[j]]&15   L3: ra=ia1[ia2[ia3[j]]]&15
// Softmax precompute folded in. Metadata written raw at paired slots;
// remap_kernel translates L2/L3 indices exactly through inv1/inv2.
__global__ void __launch_bounds__(1024, 1)
build_kernel(const float* __restrict__ w1, const float* __restrict__ w2,
             const float* __restrict__ w3,
             const int* __restrict__ ia1, const int* __restrict__ ib1,
             const int* __restrict__ ia2, const int* __restrict__ ib2,
             const int* __restrict__ ia3, const int* __restrict__ ib3)
{
    __shared__ uint16_t off[CELLS * SCNSTR];
    __shared__ uint16_t chb[CELLS * 4];
    __shared__ uint16_t csize[CELLS], exo[CELLS], ufo[CELLS];
    __shared__ uint16_t ufp[CHUNK];
    __shared__ int wte[8], wtu[8];

    const int tid  = threadIdx.x;
    const int lane = tid & 31;
    const int w    = tid >> 5;
    const uint32_t ltm = (1u << lane) - 1u;

    const int chunk = blockIdx.x;
    const int layer = (chunk < 8) ? 0 : ((chunk < 16) ? 1 : 2);
    const int baseL = (chunk - ((layer == 0) ? 0 : ((layer == 1) ? 8 : 16))) * CHUNK;
    const int j = baseL + tid;

    // indices + residue predictions
    int ia, ib; const float* wp;
    uint32_t ra, rb;
    if (layer == 0) {
        ia = __ldg(&ia1[j]); ib = __ldg(&ib1[j]); wp = w1 + (size_t)j * 16;
        ra = (uint32_t)ia & 15u; rb = (uint32_t)ib & 15u;
    } else if (layer == 1) {
        ia = __ldg(&ia2[j]); ib = __ldg(&ib2[j]); wp = w2 + (size_t)j * 16;
        ra = (uint32_t)__ldg(&ia1[ia]) & 15u;
        rb = (uint32_t)__ldg(&ia1[ib]) & 15u;
    } else {
        ia = __ldg(&ia3[j]); ib = __ldg(&ib3[j]); wp = w3 + (size_t)j * 16;
        ra = (uint32_t)__ldg(&ia1[__ldg(&ia2[ia])]) & 15u;
        rb = (uint32_t)__ldg(&ia1[__ldg(&ia2[ib])]) & 15u;
    }

    // softmax coefficients
    float v[16]; float m = -3.4e38f;
#pragma unroll
    for (int i = 0; i < 16; i++) { v[i] = wp[i]; m = fmaxf(m, v[i]); }
    float s = 0.f;
#pragma unroll
    for (int i = 0; i < 16; i++) { v[i] = expf(v[i] - m); s += v[i]; }
    float inv = 1.f / s;
    float c0 = 0.f, c1 = 0.f, c2 = 0.f, c3 = 0.f;
#pragma unroll
    for (int i = 0; i < 16; i++) {
        float p = v[i] * inv;
        c0 = fmaf(p, OPC[i][0], c0);
        c1 = fmaf(p, OPC[i][1], c1);
        c2 = fmaf(p, OPC[i][2], c2);
        c3 = fmaf(p, OPC[i][3], c3);
    }
    __half2 h01 = __floats2half2_rn(c0, c1);
    __half2 h23 = __floats2half2_rn(c2, c3);
    uint32_t u01 = *reinterpret_cast<uint32_t*>(&h01);
    uint32_t u23 = *reinterpret_cast<uint32_t*>(&h23);

    // deal (R8 core)
    for (int i = tid; i < CELLS * SCNSTR / 2; i += NTHREADS)
        reinterpret_cast<uint32_t*>(off)[i] = 0;
    __syncthreads();

    int cell = (int)(ra * 16u + rb);
    uint32_t mask = __match_any_sync(0xffffffffu, cell);
    int lr = __popc(mask & ltm);
    if ((mask & ltm) == 0)
        off[cell * SCNSTR + w] = (uint16_t)__popc(mask);
    __syncthreads();

    {   // phase 1: per-(cell, 8-warp chunk) exclusive scan
        int c  = tid >> 2;
        int ch = tid & 3;
        int bo = c * SCNSTR + ch * 8;
        uint16_t run = 0;
#pragma unroll
        for (int i = 0; i < 8; i++) {
            uint16_t t = off[bo + i];
            off[bo + i] = run;
            run = (uint16_t)(run + t);
        }
        chb[c * 4 + ch] = run;
    }
    __syncthreads();

    if (tid < CELLS) {   // phase 2: per-cell combine
        int c = tid; uint16_t bb = 0;
#pragma unroll
        for (int ch = 0; ch < 4; ch++) {
            uint16_t t = chb[c * 4 + ch];
            chb[c * 4 + ch] = bb;
            bb = (uint16_t)(bb + t);
        }
        csize[c] = bb;
        exo[c] = (bb > CAP) ? (uint16_t)(bb - CAP) : 0;
        ufo[c] = (bb < CAP) ? (uint16_t)(CAP - bb) : 0;
    }
    __syncthreads();

    {   // inclusive scans over 256 cells via warp shuffles
        int e = 0, u = 0;
        if (tid < CELLS) {
            e = exo[tid]; u = ufo[tid];
#pragma unroll
            for (int o = 1; o < 32; o <<= 1) {
                int pe = __shfl_up_sync(0xffffffffu, e, o);
                int pu = __shfl_up_sync(0xffffffffu, u, o);
                if (lane >= o) { e += pe; u += pu; }
            }
            if (lane == 31) { wte[w] = e; wtu[w] = u; }
        }
        __syncthreads();
        if (tid == 0) {
            int be = 0, bu = 0;
#pragma unroll
            for (int i = 0; i < 8; i++) {
                int te = wte[i], tu = wtu[i];
                wte[i] = be; wtu[i] = bu;
                be += te; bu += tu;
            }
        }
        __syncthreads();
        if (tid < CELLS) {
            exo[tid] = (uint16_t)(e + wte[w]);
            ufo[tid] = (uint16_t)(u + wtu[w]);
        }
    }
    __syncthreads();

    if (tid < CELLS) {   // emit unfilled dealt positions, grouped by cell
        int c = tid, t = c >> 4, ss = c & 15;
        int sz  = csize[c];
        int ufc = (sz < CAP) ? CAP - sz : 0;
        int ub  = ufo[c] - ufc;
        for (int mm = sz; mm < CAP; mm++)
            ufp[ub + (mm - sz)] = (uint16_t)((((ss - t) & 15) + 16 * mm) * 16 + t);
    }
    __syncthreads();

    int p;
    {   // assign position
        int grank = off[cell * SCNSTR + w] + chb[cell * 4 + (w >> 3)] + lr;
        int t = cell >> 4, ss = cell & 15;
        if (grank < CAP) {
            p = (((ss - t) & 15) + 16 * grank) * 16 + t;
        } else {
            int exc = csize[cell] - CAP;
            int exb = exo[cell] - exc;
            p = ufp[exb + (grank - CAP)];
        }
    }
    const int lpos = baseL + p;                  // layer-local dealt position

    // publish inv + paired metadata (raw indices)
    if (layer == 0)      d_inv1[j] = (uint16_t)lpos;
    else if (layer == 1) d_inv2[j] = (uint16_t)lpos;

    int slot, half;
    pair_slot(layer, lpos, slot, half);
    int pb = (layer == 0) ? PB1 : ((layer == 1) ? PB2 : PB3);
    g_pidx[(pb + slot) * 2 + half] = (uint32_t)ia | ((uint32_t)ib << 16);
    g_pcoef[(pb + slot) * 4 + half * 2 + 0] = u01;
    g_pcoef[(pb + slot) * 4 + half * 2 + 1] = u23;
}

// ---- remap: translate L2/L3 stored raw indices into dealt position space ---
__global__ void remap_kernel()
{
    int k = blockIdx.x * blockDim.x + threadIdx.x;   // metadata entry index
    int idx = PB2 * 2 + k;                           // skip layer-1 entries
    if (idx >= NNEUR) return;
    uint32_t pk = g_pidx[idx];
    uint32_t a, b;
    if (idx < PB3 * 2) { a = d_inv1[pk & 0xffffu]; b = d_inv1[pk >> 16]; }
    else               { a = d_inv2[pk & 0xffffu]; b = d_inv2[pk >> 16]; }
    g_pidx[idx] = a | (b << 16);
}

// -------- main kernel: strided pairing (preserves deal windows) -------------
// Metadata from PRIOR launches -> __ldg legal.

__device__ __forceinline__ uint2 one_neuron(uint32_t u01, uint32_t u23,
                                            uint2 av, uint2 bv)
{
    float2 c01 = __half22float2(*reinterpret_cast<const __half2*>(&u01));
    float2 c23 = __half22float2(*reinterpret_cast<const __half2*>(&u23));
    uint2 o;
#pragma unroll
    for (int r = 0; r < 2; r++) {
        uint32_t ua = (r == 0) ? av.x : av.y;
        uint32_t ub = (r == 0) ? bv.x : bv.y;
        float2 a = __half22float2(*reinterpret_cast<const __half2*>(&ua));
        float2 b = __half22float2(*reinterpret_cast<const __half2*>(&ub));
        float o0 = fmaf(fmaf(c23.y, b.x, c01.y), a.x, fmaf(c23.x, b.x, c01.x));
        float o1 = fmaf(fmaf(c23.y, b.y, c01.y), a.y, fmaf(c23.x, b.y, c01.x));
        __half2 h = __floats2half2_rn(o0, o1);
        uint32_t uh = *reinterpret_cast<uint32_t*>(&h);
        if (r == 0) o.x = uh; else o.y = uh;
    }
    return o;
}

struct PairIn {
    uint2 idx;
    uint4 coef;
    uint2 a0, b0, a1, b1;
};

__device__ __forceinline__ void fetch_pair(const uint2* __restrict__ src,
                                           int slot, PairIn& p)
{
    p.idx  = __ldg(reinterpret_cast<const uint2*>(g_pidx) + slot);
    p.coef = __ldg(reinterpret_cast<const uint4*>(g_pcoef) + slot);
    p.a0 = src[p.idx.x & 0xffffu];
    p.b0 = src[p.idx.x >> 16];
    p.a1 = src[p.idx.y & 0xffffu];
    p.b1 = src[p.idx.y >> 16];
}

// L1/L2: pair (pos, pos+1024) within 2048-windows; stores consecutive (coalesced).
__device__ __forceinline__ void run_layer(const uint2* __restrict__ src,
                                          uint2* __restrict__ dst,
                                          int pairBase, int tid)
{
    const int iters = D1 / 2048;                  // 4
    PairIn cur, nxt;
    fetch_pair(src, pairBase + tid, cur);
#pragma unroll
    for (int it = 0; it < iters - 1; it++) {
        fetch_pair(src, pairBase + (it + 1) * 1024 + tid, nxt);
        int pos0 = it * 2048 + tid;
        dst[pos0]        = one_neuron(cur.coef.x, cur.coef.y, cur.a0, cur.b0);
        dst[pos0 + 1024] = one_neuron(cur.coef.z, cur.coef.w, cur.a1, cur.b1);
        cur = nxt;
    }
    int pos0 = (iters - 1) * 2048 + tid;
    dst[pos0]        = one_neuron(cur.coef.x, cur.coef.y, cur.a0, cur.b0);
    dst[pos0 + 1024] = one_neuron(cur.coef.z, cur.coef.w, cur.a1, cur.b1);
}

__global__ void __launch_bounds__(NTHREADS, 1)
diff_logic_main(const float* __restrict__ x, float* __restrict__ out)
{
    extern __shared__ __align__(16) uint32_t smem_raw[];
    uint2* xs = reinterpret_cast<uint2*>(smem_raw);
    uint2* h1 = xs + D0;
    uint2* h2 = h1 + D1;
    float* wacc = reinterpret_cast<float*>(h2 + D2);   // [KCLS*16][ROWS]

    const int tid  = threadIdx.x;
    const int lane = tid & 31;
    const int row0 = blockIdx.x * ROWS;

    {
        int col = tid;                            // D0 == NTHREADS
        float v0 = __ldg(&x[(size_t)(row0 + 0) * D0 + col]);
        float v1 = __ldg(&x[(size_t)(row0 + 1) * D0 + col]);
        float v2 = __ldg(&x[(size_t)(row0 + 2) * D0 + col]);
        float v3 = __ldg(&x[(size_t)(row0 + 3) * D0 + col]);
        __half2 p0 = __floats2half2_rn(v0, v1);
        __half2 p1 = __floats2half2_rn(v2, v3);
        uint2 slot;
        slot.x = *reinterpret_cast<uint32_t*>(&p0);
        slot.y = *reinterpret_cast<uint32_t*>(&p1);
        xs[col] = slot;
    }
    __syncthreads();

    run_layer(xs, h1, PB1, tid);
    __syncthreads();
    run_layer(h1, h2, PB2, tid);
    __syncthreads();

    // Layer 3 fused with group-sum. Pairs (pos, pos+512) live in the SAME
    // group; each warp covers one group slice (512 pairs/group = 16 warps).
#pragma unroll
    for (int it = 0; it < 5; it++) {
        int q     = it * 1024 + tid;              // global pair index [0,5120)
        int group = q >> 9;
        int wig   = (q & 511) >> 5;               // warp-in-group [0,16)
        PairIn n;
        fetch_pair(h2, PB3 + q, n);

        float acc[ROWS];
        {
            float2 c01 = __half22float2(*reinterpret_cast<const __half2*>(&n.coef.x));
            float2 c23 = __half22float2(*reinterpret_cast<const __half2*>(&n.coef.y));
#pragma unroll
            for (int r = 0; r < 2; r++) {
                uint32_t ua = (r == 0) ? n.a0.x : n.a0.y;
                uint32_t ub = (r == 0) ? n.b0.x : n.b0.y;
                float2 a = __half22float2(*reinterpret_cast<const __half2*>(&ua));
                float2 b = __half22float2(*reinterpret_cast<const __half2*>(&ub));
                acc[2 * r + 0] = fmaf(fmaf(c23.y, b.x, c01.y), a.x, fmaf(c23.x, b.x, c01.x));
                acc[2 * r + 1] = fmaf(fmaf(c23.y, b.y, c01.y), a.y, fmaf(c23.x, b.y, c01.x));
            }
        }
        {
            float2 c01 = __half22float2(*reinterpret_cast<const __half2*>(&n.coef.z));
            float2 c23 = __half22float2(*reinterpret_cast<const __half2*>(&n.coef.w));
#pragma unroll
            for (int r = 0; r < 2; r++) {
                uint32_t ua = (r == 0) ? n.a1.x : n.a1.y;
                uint32_t ub = (r == 0) ? n.b1.x : n.b1.y;
                float2 a = __half22float2(*reinterpret_cast<const __half2*>(&ua));
                float2 b = __half22float2(*reinterpret_cast<const __half2*>(&ub));
                acc[2 * r + 0] += fmaf(fmaf(c23.y, b.x, c01.y), a.x, fmaf(c23.x, b.x, c01.x));
                acc[2 * r + 1] += fmaf(fmaf(c23.y, b.y, c01.y), a.y, fmaf(c23.x, b.y, c01.x));
            }
        }
#pragma unroll
        for (int r = 0; r < ROWS; r++) {
#pragma unroll
            for (int off = 16; off > 0; off >>= 1)
                acc[r] += __shfl_down_sync(0xffffffffu, acc[r], off);
        }
        if (lane == 0) {
#pragma unroll
            for (int r = 0; r < ROWS; r++)
                wacc[(group * 16 + wig) * ROWS + r] = acc[r];
        }
    }
    __syncthreads();

    if (tid < KCLS * ROWS) {
        int g = tid / ROWS;
        int r = tid - g * ROWS;
        float s = 0.f;
#pragma unroll
        for (int w = 0; w < 16; w++)
            s += wacc[(g * 16 + w) * ROWS + r];
        out[(size_t)(row0 + r) * KCLS + g] = s * (1.f / TAU);
    }
}

// -----------------------------------------------------------------------------

extern "C" void kernel_launch(void* const* d_in, const int* in_sizes, int n_in,
                              void* d_out, int out_size)
{
    (void)in_sizes; (void)n_in; (void)out_size;
    const float* x  = (const float*)d_in[0];
    const float* w1 = (const float*)d_in[1];
    const float* w2 = (const float*)d_in[2];
    const float* w3 = (const float*)d_in[3];
    const int* ia1 = (const int*)d_in[4];
    const int* ib1 = (const int*)d_in[5];
    const int* ia2 = (const int*)d_in[6];
    const int* ib2 = (const int*)d_in[7];
    const int* ia3 = (const int*)d_in[8];
    const int* ib3 = (const int*)d_in[9];
    float* out = (float*)d_out;

    build_kernel<<<NCHUNK, 1024>>>(w1, w2, w3, ia1, ib1, ia2, ib2, ia3, ib3);
    remap_kernel<<<(D2 + D3 + 255) / 256, 256>>>();

    size_t smem = (size_t)(D0 + D1 + D2) * sizeof(uint2)
                + (size_t)(KCLS * 16 * ROWS) * sizeof(float);   // ~144 KB
    cudaFuncSetAttribute(diff_logic_main, cudaFuncAttributeMaxDynamicSharedMemorySize, (int)smem);

    diff_logic_main<<<B_SZ / ROWS, NTHREADS, smem>>>(x, out);
}